// round 5
// baseline (speedup 1.0000x reference)
#include <cuda_runtime.h>
#include <cstdint>
#include <float.h>
#include <math.h>

// Problem constants (fixed by the dataset)
#define TT 64
#define UU 142
#define II 4500
#define BB 16384
#define KK 10

#define NPER 5                 // lane-major: lane owns users v = 5*lane + j
#define FULL_MASK 0xFFFFFFFFu

#define NWARPS 8192            // 1024 blocks x 8 warps
#define ROWS_PER_WARP 2        // 16384 / 8192

// order-preserving float->uint map (monotone increasing); 0 reserved as
// "invalid/selected" sentinel (all real keys for sim in [-1,1] are > 0)
__device__ __forceinline__ unsigned f2ord(float f) {
    unsigned b = __float_as_uint(f);
    return (b & 0x80000000u) ? ~b : (b | 0x80000000u);
}

__global__ __launch_bounds__(256)
void ucf_kernel(const float* __restrict__ qos,      // (T,U,I)
                const float* __restrict__ uavg,     // (T,U)
                const float* __restrict__ sim,      // (U,U)
                const int*   __restrict__ user_id,  // (B,)
                const int*   __restrict__ item_id,  // (B,)
                const int*   __restrict__ time_id,  // (B,)
                float*       __restrict__ out)      // (B,)
{
    const int gwarp = (blockIdx.x * blockDim.x + threadIdx.x) >> 5;
    const int lane  = threadIdx.x & 31;
    const int vbase = lane * NPER;

    // ---- pipeline prologue: issue gathers for row 0 ----
    int u, t;
    float qv[NPER], sv[NPER];
    {
        const int r = gwarp;
        u = __ldg(user_id + r);
        const int i = __ldg(item_id + r);
        t = __ldg(time_id + r);
        const float* __restrict__ qb = qos + (size_t)t * (UU * II) + i;
        const float* __restrict__ sr = sim + (size_t)u * UU;
        #pragma unroll
        for (int j = 0; j < NPER; j++) {
            const int v = vbase + j;
            const bool ok = (v < UU);
            qv[j] = ok ? __ldg(qb + (size_t)v * II) : 0.0f;
            sv[j] = ok ? __ldg(sr + v) : 0.0f;
        }
    }

    #pragma unroll
    for (int it = 0; it < ROWS_PER_WARP; it++) {
        const int rcur = gwarp + it * NWARPS;
        const int ucur = u;
        const int tcur = t;

        // ---- prefetch NEXT row's gathers (independent; in flight while the
        //      top-K below consumes the CURRENT row's loads) ----
        float qn[NPER], sn[NPER];
        int un = 0, tn = 0;
        if (it + 1 < ROWS_PER_WARP) {
            const int rn = gwarp + (it + 1) * NWARPS;
            un = __ldg(user_id + rn);
            const int in_ = __ldg(item_id + rn);
            tn = __ldg(time_id + rn);
            const float* __restrict__ qb = qos + (size_t)tn * (UU * II) + in_;
            const float* __restrict__ sr = sim + (size_t)un * UU;
            #pragma unroll
            for (int j = 0; j < NPER; j++) {
                const int v = vbase + j;
                const bool ok = (v < UU);
                qn[j] = ok ? __ldg(qb + (size_t)v * II) : 0.0f;
                sn[j] = ok ? __ldg(sr + v) : 0.0f;
            }
        } else {
            #pragma unroll
            for (int j = 0; j < NPER; j++) { qn[j] = 0.0f; sn[j] = 0.0f; }
        }

        // ---- consume current row ----
        float    rval[NPER];
        float    sval[NPER];
        unsigned ordu[NPER];
        #pragma unroll
        for (int j = 0; j < NPER; j++) {
            const int v = vbase + j;
            const bool ok = (v < UU);
            const float q = qv[j];
            const float s = (ok && q > 0.0f) ? sv[j] : 0.0f;
            rval[j] = q;
            sval[j] = s;
            ordu[j] = ok ? f2ord(s) : 0u;          // invalid -> sentinel 0
        }

        // iterative top-K via redux.max + ballot; tie-break lowest global
        // index (lane-major => lowest lane, strict '>' scan => lowest j)
        unsigned selmask = 0;
        float Spart = 0.0f;
        #pragma unroll
        for (int k = 0; k < KK; k++) {
            unsigned bestord = 0u;
            int bestj = 0;
            #pragma unroll
            for (int j = 0; j < NPER; j++)
                if (ordu[j] > bestord) { bestord = ordu[j]; bestj = j; }
            const unsigned maxord  = __reduce_max_sync(FULL_MASK, bestord);
            const unsigned winners = __ballot_sync(FULL_MASK, bestord == maxord);
            const int winner = __ffs(winners) - 1;
            if (lane == winner) {
                #pragma unroll
                for (int j = 0; j < NPER; j++) {
                    if (j == bestj) {
                        Spart += sval[j];
                        ordu[j] = 0u;
                        selmask |= 1u << j;
                    }
                }
            }
        }

        float S = Spart;
        #pragma unroll
        for (int off = 16; off > 0; off >>= 1)
            S += __shfl_xor_sync(FULL_MASK, S, off);
        const float denom = S + 1e-8f;

        const float* __restrict__ arow = uavg + (size_t)tcur * UU;
        float acc = 0.0f;
        #pragma unroll
        for (int j = 0; j < NPER; j++) {
            if ((selmask >> j) & 1u) {
                const int v = vbase + j;
                float w = sval[j] / denom;
                if (isnan(w))      w = 0.0f;
                else if (isinf(w)) w = copysignf(3.4028234663852886e38f, w);
                acc += w * (rval[j] - __ldg(arow + v));
            }
        }
        #pragma unroll
        for (int off = 16; off > 0; off >>= 1)
            acc += __shfl_xor_sync(FULL_MASK, acc, off);

        if (lane == 0)
            out[rcur] = __ldg(arow + ucur) + acc;

        // ---- rotate pipeline buffers ----
        u = un; t = tn;
        #pragma unroll
        for (int j = 0; j < NPER; j++) { qv[j] = qn[j]; sv[j] = sn[j]; }
    }
}

extern "C" void kernel_launch(void* const* d_in, const int* in_sizes, int n_in,
                              void* d_out, int out_size)
{
    const float* qos   = (const float*)d_in[0];  // (64,142,4500)
    const float* uavg  = (const float*)d_in[1];  // (64,142)
    const float* sim   = (const float*)d_in[2];  // (142,142)
    const int*   uid   = (const int*)  d_in[3];  // (16384,)
    const int*   iid   = (const int*)  d_in[4];  // (16384,)
    const int*   tid   = (const int*)  d_in[5];  // (16384,)
    float*       out   = (float*)d_out;          // (16384,)

    const int threads = 256;                       // 8 warps/block
    const int blocks  = (NWARPS * 32) / threads;   // 1024
    ucf_kernel<<<blocks, threads>>>(qos, uavg, sim, uid, iid, tid, out);
}

// round 8
// speedup vs baseline: 1.0182x; 1.0182x over previous
#include <cuda_runtime.h>
#include <cstdint>
#include <float.h>
#include <math.h>

// Problem constants (fixed by the dataset)
#define TT 64
#define UU 142
#define II 4500
#define BB 16384
#define KK 10

#define NPER 5                 // interleaved: lane owns users v = lane + 32*j
#define FULL_MASK 0xFFFFFFFFu

#define NWARPS 8192            // 1024 blocks x 8 warps, 2 rows per warp
#define ROWS_PER_WARP 2

// order-preserving float->uint map (monotone increasing); 0 reserved as
// "invalid" sentinel (all real keys for sim in [-1,1] are > 0)
__device__ __forceinline__ unsigned f2ord(float f) {
    unsigned b = __float_as_uint(f);
    return (b & 0x80000000u) ? ~b : (b | 0x80000000u);
}
// exact inverse of f2ord
__device__ __forceinline__ float ord2f(unsigned o) {
    return __uint_as_float((o & 0x80000000u) ? (o ^ 0x80000000u) : ~o);
}

// Process one row whose qos gathers (qv[]) are already in flight/registers.
__device__ __forceinline__ void process_row(
    const float* __restrict__ sim,
    const float* __restrict__ uavg,
    float* __restrict__ out,
    const float qv[NPER],
    int u, int t, int row, int lane)
{
    const float* __restrict__ srow = sim + (size_t)u * UU;
    const float* __restrict__ arow = uavg + (size_t)t * UU;

    // masked-sim keys; interleaved ownership v = lane + 32*j (coalesced LDGs)
    float    rval[NPER];
    unsigned ordu[NPER];
    #pragma unroll
    for (int j = 0; j < NPER; j++) {
        const int v = lane + 32 * j;
        const bool ok = (v < UU);
        const float q = qv[j];
        float s = 0.0f;
        if (ok) s = __ldg(srow + v);               // coalesced (L2-resident)
        s = (ok && q > 0.0f) ? s : 0.0f;
        rval[j] = q;
        ordu[j] = ok ? f2ord(s) : 0u;
    }

    // top-K: redux.max on key, redux.min on encoded index for exact
    // lowest-global-index tie-break (v = 32*bestj + lane ordering == v order).
    unsigned selmask = 0;
    float S = 0.0f;                                // uniform across lanes
    #pragma unroll
    for (int k = 0; k < KK; k++) {
        unsigned bestord = 0u;
        int bestj = 0;
        #pragma unroll
        for (int j = 0; j < NPER; j++) {
            if (!((selmask >> j) & 1u) && ordu[j] > bestord) {
                bestord = ordu[j]; bestj = j;
            }
        }
        const unsigned maxord = __reduce_max_sync(FULL_MASK, bestord);
        const unsigned vc = (bestord == maxord) ? (unsigned)(bestj * 32 + lane)
                                                : 0xFFFFFFFFu;
        const unsigned vwin = __reduce_min_sync(FULL_MASK, vc);
        S += ord2f(maxord);                        // descending order, all lanes
        if (lane == (int)(vwin & 31u))
            selmask |= 1u << (vwin >> 5);
    }

    const float denom = S + 1e-8f;

    // sum_k w_k * (r_k - avg_k), per-element nan_to_num(w)
    float acc = 0.0f;
    #pragma unroll
    for (int j = 0; j < NPER; j++) {
        if ((selmask >> j) & 1u) {
            const int v = lane + 32 * j;
            float w = ord2f(ordu[j]) / denom;
            if (isnan(w))      w = 0.0f;
            else if (isinf(w)) w = copysignf(3.4028234663852886e38f, w);
            acc += w * (rval[j] - __ldg(arow + v)); // coalesced
        }
    }
    #pragma unroll
    for (int off = 16; off > 0; off >>= 1)
        acc += __shfl_xor_sync(FULL_MASK, acc, off);

    if (lane == 0)
        out[row] = __ldg(arow + u) + acc;
}

__global__ __launch_bounds__(256, 7)
void ucf_kernel(const float* __restrict__ qos,      // (T,U,I)
                const float* __restrict__ uavg,     // (T,U)
                const float* __restrict__ sim,      // (U,U)
                const int*   __restrict__ user_id,  // (B,)
                const int*   __restrict__ item_id,  // (B,)
                const int*   __restrict__ time_id,  // (B,)
                float*       __restrict__ out)      // (B,)
{
    const int gwarp = (blockIdx.x * blockDim.x + threadIdx.x) >> 5;
    const int lane  = threadIdx.x & 31;

    const int r0 = gwarp;
    const int r1 = gwarp + NWARPS;

    // ids for both rows
    const int u0 = __ldg(user_id + r0);
    const int i0 = __ldg(item_id + r0);
    const int t0 = __ldg(time_id + r0);
    const int u1 = __ldg(user_id + r1);
    const int i1 = __ldg(item_id + r1);
    const int t1 = __ldg(time_id + r1);
    // pack row-1 ids into one register (t<64, u<142, i<4500)
    const unsigned packed1 = ((unsigned)t1 << 22) | ((unsigned)u1 << 14) | (unsigned)i1;

    // issue ALL 10 qos gathers up front (both rows in flight together)
    const float* __restrict__ qb0 = qos + (size_t)t0 * (UU * II) + i0;
    const float* __restrict__ qb1 = qos + (size_t)t1 * (UU * II) + i1;
    float q0[NPER], q1[NPER];
    #pragma unroll
    for (int j = 0; j < NPER; j++) {
        const int v = lane + 32 * j;
        const bool ok = (v < UU);
        q0[j] = ok ? __ldg(qb0 + (size_t)v * II) : 0.0f;
        q1[j] = ok ? __ldg(qb1 + (size_t)v * II) : 0.0f;
    }

    // row 0 compute — row 1's gathers remain outstanding throughout
    process_row(sim, uavg, out, q0, u0, t0, r0, lane);

    // row 1 compute
    const int tu1 = (int)(packed1 >> 22);
    const int uu1 = (int)((packed1 >> 14) & 0xFFu);
    process_row(sim, uavg, out, q1, uu1, tu1, r1, lane);
}

extern "C" void kernel_launch(void* const* d_in, const int* in_sizes, int n_in,
                              void* d_out, int out_size)
{
    const float* qos   = (const float*)d_in[0];  // (64,142,4500)
    const float* uavg  = (const float*)d_in[1];  // (64,142)
    const float* sim   = (const float*)d_in[2];  // (142,142)
    const int*   uid   = (const int*)  d_in[3];  // (16384,)
    const int*   iid   = (const int*)  d_in[4];  // (16384,)
    const int*   tid   = (const int*)  d_in[5];  // (16384,)
    float*       out   = (float*)d_out;          // (16384,)

    const int threads = 256;                       // 8 warps/block
    const int blocks  = (NWARPS * 32) / threads;   // 1024 -> single wave @7/SM
    ucf_kernel<<<blocks, threads>>>(qos, uavg, sim, uid, iid, tid, out);
}

// round 9
// speedup vs baseline: 1.9551x; 1.9201x over previous
#include <cuda_runtime.h>
#include <cstdint>
#include <float.h>
#include <math.h>

// Problem constants (fixed by the dataset)
#define TT 64
#define UU 142
#define II 4500
#define BB 16384
#define KK 10

#define NPER 5                 // interleaved: lane owns users v = lane + 32*j
#define FULL_MASK 0xFFFFFFFFu

// Candidate threshold: sims are 0.5(s+s^T) ~ triangular(-1,1).
// P(sim > 0.35) = (1-0.35)^2/2 = 0.211 -> E[|C|] ~ 30, E[rated in C] ~ 21.
// P(<10 rated candidates) ~ 0.5-1% -> fallback full path (exact, rare).
#define THETA 0.35f

// order-preserving float->uint map (monotone increasing); 0 reserved as
// "invalid" sentinel (all real masked-sim keys are > 0: f2ord(0.0)=0x80000000)
__device__ __forceinline__ unsigned f2ord(float f) {
    unsigned b = __float_as_uint(f);
    return (b & 0x80000000u) ? ~b : (b | 0x80000000u);
}
// exact inverse of f2ord
__device__ __forceinline__ float ord2f(unsigned o) {
    return __uint_as_float((o & 0x80000000u) ? (o ^ 0x80000000u) : ~o);
}

__global__ __launch_bounds__(256)
void ucf_kernel(const float* __restrict__ qos,      // (T,U,I)
                const float* __restrict__ uavg,     // (T,U)
                const float* __restrict__ sim,      // (U,U)
                const int*   __restrict__ user_id,  // (B,)
                const int*   __restrict__ item_id,  // (B,)
                const int*   __restrict__ time_id,  // (B,)
                float*       __restrict__ out)      // (B,)
{
    const int warp = (blockIdx.x * blockDim.x + threadIdx.x) >> 5;
    const int lane = threadIdx.x & 31;
    if (warp >= BB) return;

    const int u = __ldg(user_id + warp);
    const int i = __ldg(item_id + warp);
    const int t = __ldg(time_id + warp);

    const float* __restrict__ qbase = qos + (size_t)t * (UU * II) + i;
    const float* __restrict__ srow  = sim + (size_t)u * UU;
    const float* __restrict__ arow  = uavg + (size_t)t * UU;

    // 1) sim row (coalesced, L2-resident)
    float sv[NPER];
    #pragma unroll
    for (int j = 0; j < NPER; j++) {
        const int v = lane + 32 * j;
        sv[j] = (v < UU) ? __ldg(srow + v) : 0.0f;
    }

    // 2) candidates: sim > THETA; probe qos ONLY for candidates
    unsigned candmask = 0;
    #pragma unroll
    for (int j = 0; j < NPER; j++) {
        const int v = lane + 32 * j;
        if (v < UU && sv[j] > THETA) candmask |= 1u << j;
    }

    float qv[NPER];
    #pragma unroll
    for (int j = 0; j < NPER; j++) {
        const int v = lane + 32 * j;
        qv[j] = ((candmask >> j) & 1u) ? __ldg(qbase + (size_t)v * II) : 0.0f;
    }

    // 3) count rated candidates (warp-uniform)
    int cnt = 0;
    #pragma unroll
    for (int j = 0; j < NPER; j++)
        cnt += __popc(__ballot_sync(FULL_MASK,
                      ((candmask >> j) & 1u) && qv[j] > 0.0f));

    // 4) build keys; fast path if the top-10 is provably among rated candidates
    unsigned ordu[NPER];
    if (cnt >= KK) {
        // Any non-candidate is unrated (masked 0 < THETA) or rated with
        // sim <= THETA < candidate sims -> cannot displace rated candidates.
        #pragma unroll
        for (int j = 0; j < NPER; j++) {
            const bool rc = ((candmask >> j) & 1u) && qv[j] > 0.0f;
            ordu[j] = rc ? f2ord(sv[j]) : 0u;
        }
    } else {
        // Rare exact fallback: load everything, full masked top-K semantics
        #pragma unroll
        for (int j = 0; j < NPER; j++) {
            const int v = lane + 32 * j;
            qv[j] = (v < UU) ? __ldg(qbase + (size_t)v * II) : 0.0f;
        }
        #pragma unroll
        for (int j = 0; j < NPER; j++) {
            const int v = lane + 32 * j;
            const bool ok = (v < UU);
            const float m = (ok && qv[j] > 0.0f) ? sv[j] : 0.0f;
            ordu[j] = ok ? f2ord(m) : 0u;
        }
    }

    // 5) top-K: redux.max on key, redux.min on encoded index
    //    (v = 32*bestj + lane == global user index -> lowest-index tie-break)
    unsigned selmask = 0;
    float S = 0.0f;                                // uniform across lanes
    #pragma unroll
    for (int k = 0; k < KK; k++) {
        unsigned bestord = 0u;
        int bestj = 0;
        #pragma unroll
        for (int j = 0; j < NPER; j++) {
            if (!((selmask >> j) & 1u) && ordu[j] > bestord) {
                bestord = ordu[j]; bestj = j;
            }
        }
        const unsigned maxord = __reduce_max_sync(FULL_MASK, bestord);
        const unsigned vc = (bestord == maxord) ? (unsigned)(bestj * 32 + lane)
                                                : 0xFFFFFFFFu;
        const unsigned vwin = __reduce_min_sync(FULL_MASK, vc);
        S += ord2f(maxord);                        // k-th largest, all lanes
        if (lane == (int)(vwin & 31u))
            selmask |= 1u << (vwin >> 5);
    }

    const float denom = S + 1e-8f;

    // 6) epilogue: sum_k w_k * (r_k - avg_k), per-element nan_to_num(w)
    float acc = 0.0f;
    #pragma unroll
    for (int j = 0; j < NPER; j++) {
        if ((selmask >> j) & 1u) {
            const int v = lane + 32 * j;
            float w = ord2f(ordu[j]) / denom;
            if (isnan(w))      w = 0.0f;
            else if (isinf(w)) w = copysignf(3.4028234663852886e38f, w);
            acc += w * (qv[j] - __ldg(arow + v));  // coalesced, L2
        }
    }
    #pragma unroll
    for (int off = 16; off > 0; off >>= 1)
        acc += __shfl_xor_sync(FULL_MASK, acc, off);

    if (lane == 0)
        out[warp] = __ldg(arow + u) + acc;
}

extern "C" void kernel_launch(void* const* d_in, const int* in_sizes, int n_in,
                              void* d_out, int out_size)
{
    const float* qos   = (const float*)d_in[0];  // (64,142,4500)
    const float* uavg  = (const float*)d_in[1];  // (64,142)
    const float* sim   = (const float*)d_in[2];  // (142,142)
    const int*   uid   = (const int*)  d_in[3];  // (16384,)
    const int*   iid   = (const int*)  d_in[4];  // (16384,)
    const int*   tid   = (const int*)  d_in[5];  // (16384,)
    float*       out   = (float*)d_out;          // (16384,)

    const int threads = 256;                 // 8 warps/block, 1 warp per row
    const int blocks  = (BB * 32) / threads; // 2048
    ucf_kernel<<<blocks, threads>>>(qos, uavg, sim, uid, iid, tid, out);
}